// round 4
// baseline (speedup 1.0000x reference)
#include <cuda_runtime.h>
#include <cstdint>

// Problem shape (fixed for this dataset entry)
#define B_ 4
#define C_ 32
#define H_ 256
#define W_ 512
#define D_ 48

#define WT   128            // w-tile per block
#define TW   (WT + D_)      // 176: h1 tile width (window overhang)
#define TWP  (TW + 1)       // 177: padded stride -> conflict-free (gcd(17,32)=1)
#define NTHREADS 256

// --- packed f32x2 helpers (FFMA2 is PTX-only; ptxas never auto-fuses) ---
__device__ __forceinline__ void fma2(unsigned long long &acc,
                                     unsigned long long a,
                                     unsigned long long b) {
    asm("fma.rn.f32x2 %0, %1, %2, %0;" : "+l"(acc) : "l"(a), "l"(b));
}
__device__ __forceinline__ unsigned long long pack2(float lo, float hi) {
    unsigned long long r;
    asm("mov.b64 %0, {%1, %2};"
        : "=l"(r) : "r"(__float_as_uint(lo)), "r"(__float_as_uint(hi)));
    return r;
}

__global__ void __launch_bounds__(NTHREADS)
dense_warp_kernel(const float* __restrict__ h1,
                  const float* __restrict__ cost,
                  float* __restrict__ out) {
    __shared__ __align__(16) float cost_s[D_ * WT];   // 24 KB
    __shared__ __align__(16) float h1_s[C_ * TWP];    // 22.6 KB

    const int bx    = blockIdx.x;
    const int wt    = bx & 3;                 // W_/WT = 4 tiles
    const int h     = (bx >> 2) & (H_ - 1);
    const int b     = bx >> 10;               // /(4*256)
    const int wbase = wt * WT;
    const int tid   = threadIdx.x;

    // ---- load cost tile [D_ x WT] (float4, coalesced) ----
    {
        const float* cbase = cost + ((size_t)(b * D_) * H_ + h) * W_ + wbase;
        #pragma unroll
        for (int idx = tid; idx < (D_ * WT) / 4; idx += NTHREADS) {
            int dd = idx >> 5;               // WT/4 = 32 float4 per row
            int ww = (idx & 31) << 2;
            *(float4*)&cost_s[dd * WT + ww] =
                *(const float4*)&cbase[(size_t)dd * (H_ * W_) + ww];
        }
    }
    // ---- load h1 tile [C_ x TW], zero-padded past W (handles w+d >= W) ----
    {
        const float* hbase = h1 + ((size_t)(b * C_) * H_ + h) * W_ + wbase;
        for (int idx = tid; idx < C_ * TW; idx += NTHREADS) {
            int cc = idx / TW;
            int x  = idx - cc * TW;
            float v = 0.0f;
            if (wbase + x < W_) v = hbase[(size_t)cc * (H_ * W_) + x];
            h1_s[cc * TWP + x] = v;
        }
    }
    __syncthreads();

    // warp = 32 channels at one w-sublane: cost reads broadcast, h1 conflict-free
    const int c  = tid & 31;
    const int wl = tid >> 5;        // 0..7
    const int w0 = wl * 16;

    const float* hr = &h1_s[c * TWP + w0];

    // 16-deep sliding register window over h1
    float win[16];
    #pragma unroll
    for (int j = 0; j < 16; j++) win[j] = hr[j];

    unsigned long long acc[8];
    #pragma unroll
    for (int j = 0; j < 8; j++) acc[j] = 0ull;

    // invariant entering step d: win[(d+k)&15] == h1[w0+d+k], k=0..15
    #pragma unroll 1
    for (int d0 = 0; d0 < D_; d0 += 16) {
        #pragma unroll
        for (int dd = 0; dd < 16; dd++) {
            // cost pairs: little-endian u64 == (cost[w], cost[w+1]) as f32x2
            const ulonglong2* cp =
                (const ulonglong2*)&cost_s[(d0 + dd) * WT + w0];
            ulonglong2 q0 = cp[0], q1 = cp[1], q2 = cp[2], q3 = cp[3];

            fma2(acc[0], q0.x, pack2(win[(dd + 0)  & 15], win[(dd + 1)  & 15]));
            fma2(acc[1], q0.y, pack2(win[(dd + 2)  & 15], win[(dd + 3)  & 15]));
            fma2(acc[2], q1.x, pack2(win[(dd + 4)  & 15], win[(dd + 5)  & 15]));
            fma2(acc[3], q1.y, pack2(win[(dd + 6)  & 15], win[(dd + 7)  & 15]));
            fma2(acc[4], q2.x, pack2(win[(dd + 8)  & 15], win[(dd + 9)  & 15]));
            fma2(acc[5], q2.y, pack2(win[(dd + 10) & 15], win[(dd + 11) & 15]));
            fma2(acc[6], q3.x, pack2(win[(dd + 12) & 15], win[(dd + 13) & 15]));
            fma2(acc[7], q3.y, pack2(win[(dd + 14) & 15], win[(dd + 15) & 15]));

            // slide: replace oldest (index d&15 == dd) with h1[w0 + d + 16]
            win[dd] = hr[16 + d0 + dd];
        }
    }

    // ---- store 16 contiguous floats per thread (4x STG.128) ----
    float* orow = out + (((size_t)b * C_ + c) * H_ + h) * W_ + wbase + w0;
    ulonglong2* ov = (ulonglong2*)orow;
    ov[0] = make_ulonglong2(acc[0], acc[1]);
    ov[1] = make_ulonglong2(acc[2], acc[3]);
    ov[2] = make_ulonglong2(acc[4], acc[5]);
    ov[3] = make_ulonglong2(acc[6], acc[7]);
}

extern "C" void kernel_launch(void* const* d_in, const int* in_sizes, int n_in,
                              void* d_out, int out_size) {
    (void)in_sizes; (void)n_in; (void)out_size;
    const float* h1   = (const float*)d_in[0];
    const float* cost = (const float*)d_in[1];
    float* out        = (float*)d_out;

    const int nblocks = B_ * H_ * (W_ / WT);   // 4096
    dense_warp_kernel<<<nblocks, NTHREADS>>>(h1, cost, out);
}